// round 15
// baseline (speedup 1.0000x reference)
#include <cuda_runtime.h>
#include <cuda_bf16.h>
#include <cuda_fp16.h>
#include <cstdint>

#define F 96
#define G3 288            // 3*F
#define NN 50000
#define EE 800000

typedef unsigned long long u64;
typedef unsigned int u32;

// ---------------- scratch (static __device__ — no allocs allowed) ----------------
__device__ float g_ab [NN * 2 * F];   // [N,192]: cols 0..95 = Ah, 96..191 = Bh
__device__ float g_h  [NN * F];       // aggregated node state
__device__ float g_gi1[NN * G3];      // used as uint4[NN][48]: {r,z,n,pad} half2 per feature pair
__device__ float g_gi2[NN * G3];
__device__ u32   g_e2h[(size_t)EE * 48];   // e2 in half2 pairs
__device__ float g_stats[4 * F];      // [hsum, hsumsq, esum, esumsq]

__device__ __forceinline__ float tanhap(float x) {        // 1 MUFU op
    float y;
    asm("tanh.approx.f32 %0, %1;" : "=f"(y) : "f"(x));
    return y;
}
__device__ __forceinline__ float sig_t(float x) {         // 1 MUFU + 2 FMA
    return fmaf(tanhap(0.5f * x), 0.5f, 0.5f);
}
__device__ __forceinline__ u32 smem_u32(const void* p) {
    u32 a;
    asm("{ .reg .u64 t; cvta.to.shared.u64 t, %1; cvt.u32.u64 %0, t; }" : "=r"(a) : "l"(p));
    return a;
}
__device__ __forceinline__ void barg(int id) {            // 4-warp group barrier
    asm volatile("bar.sync %0, %1;" :: "r"(id), "r"(128) : "memory");
}
__device__ __forceinline__ void cpasync16(u32 s, const void* g) {
    asm volatile("cp.async.cg.shared.global [%0], [%1], 16;" :: "r"(s), "l"(g));
}
#define CP_COMMIT() asm volatile("cp.async.commit_group;" ::: "memory")
#define CP_WAIT0()  asm volatile("cp.async.wait_group 0;" ::: "memory")

// warp-level tensor ops (portable PTX at compute_103 -> HMMA on sm_103a)
__device__ __forceinline__ void ldm4(u32* r, u32 a) {
    asm volatile("ldmatrix.sync.aligned.m8n8.x4.shared.b16 {%0,%1,%2,%3}, [%4];"
        : "=r"(r[0]), "=r"(r[1]), "=r"(r[2]), "=r"(r[3]) : "r"(a));
}
__device__ __forceinline__ void ldm2(u32* r, u32 a) {
    asm volatile("ldmatrix.sync.aligned.m8n8.x2.shared.b16 {%0,%1}, [%2];"
        : "=r"(r[0]), "=r"(r[1]) : "r"(a));
}
__device__ __forceinline__ void mma_f16(float* c, const u32* a, const u32* b) {
    asm volatile("mma.sync.aligned.m16n8k16.row.col.f32.f16.f16.f32 "
        "{%0,%1,%2,%3}, {%4,%5,%6,%7}, {%8,%9}, {%0,%1,%2,%3};"
        : "+f"(c[0]), "+f"(c[1]), "+f"(c[2]), "+f"(c[3])
        : "r"(a[0]), "r"(a[1]), "r"(a[2]), "r"(a[3]), "r"(b[0]), "r"(b[1]));
}

__global__ void zero_stats_kernel() { g_stats[threadIdx.x] = 0.f; }

__device__ __forceinline__ u32 toh2(float2 x) {
    __half2 h = __floats2half2_rn(x.x, x.y);
    return *(u32*)&h;
}
// gate-interleave permutation of a [288] row index
__device__ __forceinline__ int permute_row(int n) {
    int g = n / 96, rem = n - g * 96, w = rem / 24, t = rem - w * 24;
    return w * 72 + ((t >> 3) + 3 * g) * 8 + (t & 7);
}

#define AST 104    // padded smem row stride in 16-bit units (208B, conflict-free ldmatrix)

// =================== fp16 AB GEMM: Y[R,192] = X @ [A_w;B_w].T + [A_b;B_b] ===================
__global__ __launch_bounds__(512)
void gemm_ab_f16(const float* __restrict__ X,
                 const float* __restrict__ W0, const float* __restrict__ W1,
                 const float* __restrict__ b0, const float* __restrict__ b1,
                 float* __restrict__ Y, int R, int ntiles)
{
    constexpr int COUT = 192, NT = 6;
    constexpr int BSZ = COUT * AST * 2;    // 39936
    extern __shared__ char smem[];
    u32 sb = smem_u32(smem);
    const int OF_A = BSZ, OF_BS = BSZ + 26624;
    float* bs = (float*)(smem + OF_BS);
    int tid = threadIdx.x, wid = tid >> 5, lane = tid & 31;

    for (int i = tid; i < COUT * 48; i += 512) {
        int n = i / 48, j = i - n * 48, k = 2 * j;
        float2 w2 = (n < 96) ? *(const float2*)(W0 + n * F + k)
                             : *(const float2*)(W1 + (n - 96) * F + k);
        *(u32*)(smem + (u32)(n * AST + k) * 2) = toh2(w2);
    }
    for (int i = tid; i < COUT; i += 512)
        bs[i] = (i < 96) ? b0[i] : b1[i - 96];
    __syncthreads();

    int wM = wid & 3, wN = wid >> 2;
    int a_row = ((lane >> 3) & 1) * 8 + (lane & 7);
    int a_kof = (lane >> 4) * 8;
    int b4r   = (lane & 7) + ((lane >> 4) << 3);

    for (int t = blockIdx.x; t < ntiles; t += gridDim.x) {
        int base = t * 128;
        #pragma unroll
        for (int q = 0; q < 12; ++q) {
            int i = tid + 512 * q;
            int r = i / 48, j = i - r * 48, k = 2 * j;
            float2 x2 = (base + r < R) ? *(const float2*)(X + (size_t)(base + r) * F + k)
                                       : make_float2(0.f, 0.f);
            *(u32*)(smem + OF_A + (u32)(r * AST + k) * 2) = toh2(x2);
        }
        __syncthreads();

        float acc[2][NT][4];
        #pragma unroll
        for (int mt = 0; mt < 2; ++mt)
            #pragma unroll
            for (int j = 0; j < NT; ++j)
                #pragma unroll
                for (int c = 0; c < 4; ++c) acc[mt][j][c] = 0.f;

        #pragma unroll
        for (int ks = 0; ks < 6; ++ks) {
            u32 ah[2][4];
            #pragma unroll
            for (int mt = 0; mt < 2; ++mt) {
                u32 ro = (u32)((32 * wM + mt * 16 + a_row) * AST + ks * 16 + a_kof) * 2;
                ldm4(ah[mt], sb + OF_A + ro);
            }
            #pragma unroll
            for (int jp = 0; jp < 3; ++jp) {
                u32 ro = (u32)((wN * 48 + jp * 16 + b4r) * AST + ks * 16
                               + ((lane >> 3) & 1) * 8) * 2;
                u32 bh[4];
                ldm4(bh, sb + ro);
                #pragma unroll
                for (int mt = 0; mt < 2; ++mt) {
                    mma_f16(acc[mt][2 * jp],     ah[mt], bh);
                    mma_f16(acc[mt][2 * jp + 1], ah[mt], bh + 2);
                }
            }
        }

        #pragma unroll
        for (int mt = 0; mt < 2; ++mt)
            #pragma unroll
            for (int hf = 0; hf < 2; ++hf) {
                int r = base + 32 * wM + mt * 16 + hf * 8 + (lane >> 2);
                if (r < R) {
                    #pragma unroll
                    for (int j = 0; j < NT; ++j) {
                        int f = wN * 48 + j * 8 + 2 * (lane & 3);
                        float2 v;
                        v.x = acc[mt][j][2 * hf]     + bs[f];
                        v.y = acc[mt][j][2 * hf + 1] + bs[f + 1];
                        *(float2*)(Y + (size_t)r * COUT + f) = v;
                    }
                }
            }
        __syncthreads();
    }
}

// =================== merged fp16 gi GEMM: both W1/W2, shared A conversion ===================
#define GIK_B1 0            // 59904
#define GIK_B2 59904        // -> 119808
#define GIK_A  119808       // 26624 -> 146432
#define GIK_BS 146432       // 2*288 floats -> +2304 = 148736
#define GIK_TOT 148736

__global__ __launch_bounds__(512)
void gemm_gi_f16g(const float* __restrict__ X,
                  const float* __restrict__ W1, const float* __restrict__ b1,
                  const float* __restrict__ W2, const float* __restrict__ b2,
                  uint4* __restrict__ Y1, uint4* __restrict__ Y2, int R, int ntiles)
{
    extern __shared__ char smem[];
    u32 sb = smem_u32(smem);
    float* bsP = (float*)(smem + GIK_BS);
    int tid = threadIdx.x, wid = tid >> 5, lane = tid & 31;

    for (int i = tid; i < G3 * 48; i += 512) {
        int n = i / 48, j = i - n * 48, k = 2 * j;
        int p = permute_row(n);
        u32 off = (u32)(p * AST + k) * 2;
        *(u32*)(smem + GIK_B1 + off) = toh2(*(const float2*)(W1 + n * F + k));
        *(u32*)(smem + GIK_B2 + off) = toh2(*(const float2*)(W2 + n * F + k));
    }
    for (int i = tid; i < G3; i += 512) {
        bsP[permute_row(i)]       = b1[i];
        bsP[288 + permute_row(i)] = b2[i];
    }
    __syncthreads();

    int wM = wid & 3, wN = wid >> 2;
    int a_row = ((lane >> 3) & 1) * 8 + (lane & 7);
    int a_kof = (lane >> 4) * 8;
    int b4r   = (lane & 7) + ((lane >> 4) << 3);
    int b_row = lane & 7;
    int b_kof = ((lane >> 3) & 1) * 8;

    for (int t = blockIdx.x; t < ntiles; t += gridDim.x) {
        int base = t * 128;
        #pragma unroll
        for (int q = 0; q < 12; ++q) {
            int i = tid + 512 * q;
            int r = i / 48, j = i - r * 48, k = 2 * j;
            float2 x2 = (base + r < R) ? *(const float2*)(X + (size_t)(base + r) * F + k)
                                       : make_float2(0.f, 0.f);
            *(u32*)(smem + GIK_A + (u32)(r * AST + k) * 2) = toh2(x2);
        }
        __syncthreads();

        #pragma unroll
        for (int gg = 0; gg < 2; ++gg) {
            u32 bb = sb + (gg ? GIK_B2 : GIK_B1);
            const float* bsc = bsP + gg * 288;
            uint4* Yo = gg ? Y2 : Y1;

            float acc[2][9][4];
            #pragma unroll
            for (int mt = 0; mt < 2; ++mt)
                #pragma unroll
                for (int j = 0; j < 9; ++j)
                    #pragma unroll
                    for (int c = 0; c < 4; ++c) acc[mt][j][c] = 0.f;

            #pragma unroll
            for (int ks = 0; ks < 6; ++ks) {
                u32 ah[2][4];
                #pragma unroll
                for (int mt = 0; mt < 2; ++mt) {
                    u32 ro = (u32)((32 * wM + mt * 16 + a_row) * AST + ks * 16 + a_kof) * 2;
                    ldm4(ah[mt], sb + GIK_A + ro);
                }
                #pragma unroll
                for (int jp = 0; jp < 4; ++jp) {
                    u32 ro = (u32)((wN * 72 + jp * 16 + b4r) * AST + ks * 16 + b_kof) * 2;
                    u32 bh[4];
                    ldm4(bh, bb + ro);
                    #pragma unroll
                    for (int mt = 0; mt < 2; ++mt) {
                        mma_f16(acc[mt][2 * jp],     ah[mt], bh);
                        mma_f16(acc[mt][2 * jp + 1], ah[mt], bh + 2);
                    }
                }
                {
                    u32 ro = (u32)((wN * 72 + 64 + b_row) * AST + ks * 16 + b_kof) * 2;
                    u32 bh[2];
                    ldm2(bh, bb + ro);
                    #pragma unroll
                    for (int mt = 0; mt < 2; ++mt)
                        mma_f16(acc[mt][8], ah[mt], bh);
                }
            }

            #pragma unroll
            for (int mt = 0; mt < 2; ++mt)
                #pragma unroll
                for (int hf = 0; hf < 2; ++hf) {
                    int r = base + 32 * wM + mt * 16 + hf * 8 + (lane >> 2);
                    if (r < R) {
                        #pragma unroll
                        for (int fg = 0; fg < 3; ++fg) {
                            int c = wN * 72 + fg * 8 + 2 * (lane & 3);
                            float2 vr, vz, vn;
                            vr.x = acc[mt][fg][2 * hf]         + bsc[c];
                            vr.y = acc[mt][fg][2 * hf + 1]     + bsc[c + 1];
                            vz.x = acc[mt][3 + fg][2 * hf]     + bsc[c + 24];
                            vz.y = acc[mt][3 + fg][2 * hf + 1] + bsc[c + 25];
                            vn.x = acc[mt][6 + fg][2 * hf]     + bsc[c + 48];
                            vn.y = acc[mt][6 + fg][2 * hf + 1] + bsc[c + 49];
                            uint4 o;
                            o.x = toh2(vr); o.y = toh2(vz); o.z = toh2(vn); o.w = 0;
                            Yo[(size_t)r * 48 + wN * 12 + fg * 4 + (lane & 3)] = o;
                        }
                    }
                }
        }
        __syncthreads();
    }
}

// =================== FUSED fp16 edge kernel: independent 32-edge group streams ===============
// Each 128-thread group (wM) is a virtual block: own tile stream (32-edge tiles), own smem
// row region, own gi2 staging, group-local barriers. Only weights are shared.
#define SM_B1  0            // 59904
#define SM_B2  59904        // -> 119808
#define SM_A   119808       // 26624 -> 146432
#define SM_E   146432       // 26624 -> 173056
#define SM_STG 173056       // 49152 -> 222208
#define SM_BS  222208       // 2304 -> 224512
#define SM_ST  224512       // 768 -> 225280
#define SM_GI2 225280       // 6144 -> 231424
#define SM_TOT 231424

__global__ __launch_bounds__(512)
void edge_gru2_mma(const float* __restrict__ ef,
                   const uint4* __restrict__ gi1_all, const uint4* __restrict__ gi2_all,
                   const int* __restrict__ src,
                   const float* __restrict__ W1, const float* __restrict__ b1,
                   const float* __restrict__ W2, const float* __restrict__ b2,
                   u32* __restrict__ oute, int ntiles32)
{
    extern __shared__ char smem[];
    u32 sb = smem_u32(smem);
    int tid = threadIdx.x, wid = tid >> 5, lane = tid & 31;
    float* bs1 = (float*)(smem + SM_BS);
    float* bs2 = bs1 + G3;
    float* st  = (float*)(smem + SM_ST);

    int wM = wid & 3, wN = wid >> 2;
    int gt = wN * 32 + lane;            // 0..127 within group
    int bid = 1 + wM;

    // ---- W1, W2 -> permuted fp16 (once per block) ----
    for (int i = tid; i < G3 * 48; i += 512) {
        int n = i / 48, j = i - n * 48, k = 2 * j;
        int p = permute_row(n);
        u32 off = (u32)(p * AST + k) * 2;
        *(u32*)(smem + SM_B1 + off) = toh2(*(const float2*)(W1 + n * F + k));
        *(u32*)(smem + SM_B2 + off) = toh2(*(const float2*)(W2 + n * F + k));
    }
    for (int i = tid; i < G3; i += 512) { bs1[i] = b1[i]; bs2[i] = b2[i]; }
    if (tid < 192) st[tid] = 0.f;

    // group stream: tile index g0, stride
    int g0 = blockIdx.x * 4 + wM;
    int gstep = gridDim.x * 4;

    // prologue: group converts its first 32-edge tile into its A rows
    if (g0 < ntiles32) {
        size_t e0 = (size_t)g0 * 32;
        #pragma unroll
        for (int q = 0; q < 12; ++q) {
            int i = gt + 128 * q;
            int rl = i / 48, j = i - rl * 48, k = 2 * j;
            *(u32*)(smem + SM_A + (u32)(((32 * wM + rl) * AST + k) * 2))
                = toh2(*(const float2*)(ef + (e0 + rl) * F + k));
        }
    }
    __syncthreads();

    int a_row = ((lane >> 3) & 1) * 8 + (lane & 7);
    int a_kof = (lane >> 4) * 8;
    int b4r   = (lane & 7) + ((lane >> 4) << 3);
    int b_row = lane & 7;
    int b_kof = ((lane >> 3) & 1) * 8;
    float2 s1[3], s2[3];
    #pragma unroll
    for (int i = 0; i < 3; ++i) { s1[i] = make_float2(0.f, 0.f); s2[i] = make_float2(0.f, 0.f); }

    char*  gi2s = smem + SM_GI2 + wM * 2 * 48 * 16;
    float* stg  = (float*)(smem + SM_STG + wM * 12288);

    for (int t = g0; t < ntiles32; t += gstep) {
        size_t e0 = (size_t)t * 32;
        int tn = t + gstep;

        // ---- cp.async next raw 32-edge tile into group STG ----
        if (tn < ntiles32) {
            const char* gsrc = (const char*)(ef + (size_t)tn * 32 * F);
            u32 sdst = sb + SM_STG + (u32)wM * 12288;
            #pragma unroll
            for (int q = 0; q < 6; ++q) {
                int i = gt + 128 * q;
                cpasync16(sdst + i * 16, gsrc + i * 16);
            }
        }
        CP_COMMIT();

        // ---- stage gi2 for the group's 2 dst nodes (dst = edge/16) ----
        if (gt < 96) {
            int nl = gt / 48, pr = gt - nl * 48;
            int node = (int)(e0 >> 4) + nl;
            *(uint4*)(gi2s + (size_t)(nl * 48 + pr) * 16)
                = __ldg(gi2_all + (size_t)node * 48 + pr);
        }
        // ---- prefetch src indices / gi1 row pointers ----
        const uint4* gi1p[4];
        #pragma unroll
        for (int mh = 0; mh < 4; ++mh) {
            int rl = (mh >> 1) * 16 + (mh & 1) * 8 + (lane >> 2);
            gi1p[mh] = gi1_all + (size_t)__ldg(&src[e0 + rl]) * 48;
        }

        float acc[2][9][4];
        u32 v1p[2][2][3];

        // ============ layer 1 (A rows of this group) ============
        #pragma unroll
        for (int mt = 0; mt < 2; ++mt)
            #pragma unroll
            for (int j = 0; j < 9; ++j)
                #pragma unroll
                for (int c = 0; c < 4; ++c) acc[mt][j][c] = 0.f;

        #pragma unroll
        for (int ks = 0; ks < 6; ++ks) {
            u32 ah[2][4];
            #pragma unroll
            for (int mt = 0; mt < 2; ++mt) {
                u32 ro = (u32)((32 * wM + mt * 16 + a_row) * AST + ks * 16 + a_kof) * 2;
                ldm4(ah[mt], sb + SM_A + ro);
            }
            #pragma unroll
            for (int jp = 0; jp < 4; ++jp) {
                u32 ro = (u32)((wN * 72 + jp * 16 + b4r) * AST + ks * 16 + b_kof) * 2;
                u32 bh[4];
                ldm4(bh, sb + SM_B1 + ro);
                #pragma unroll
                for (int mt = 0; mt < 2; ++mt) {
                    mma_f16(acc[mt][2 * jp],     ah[mt], bh);
                    mma_f16(acc[mt][2 * jp + 1], ah[mt], bh + 2);
                }
            }
            {
                u32 ro = (u32)((wN * 72 + 64 + b_row) * AST + ks * 16 + b_kof) * 2;
                u32 bh[2];
                ldm2(bh, sb + SM_B1 + ro);
                #pragma unroll
                for (int mt = 0; mt < 2; ++mt)
                    mma_f16(acc[mt][8], ah[mt], bh);
            }
        }

        // GRU1 epilogue -> v1p; store e1 into E (group rows)
        #pragma unroll
        for (int mt = 0; mt < 2; ++mt) {
            #pragma unroll
            for (int hf = 0; hf < 2; ++hf) {
                int rl = mt * 16 + hf * 8 + (lane >> 2);
                int r = 32 * wM + rl;
                const uint4* gi = gi1p[mt * 2 + hf];
                #pragma unroll
                for (int fg = 0; fg < 3; ++fg) {
                    int f = wN * 24 + fg * 8 + 2 * (lane & 3);
                    uint4 gv = __ldg(gi + wN * 12 + fg * 4 + (lane & 3));
                    float2 gir = __half22float2(*(__half2*)&gv.x);
                    float2 giz = __half22float2(*(__half2*)&gv.y);
                    float2 gin = __half22float2(*(__half2*)&gv.z);
                    float2 pv  = __half22float2(*(__half2*)(smem + SM_A + (u32)((r * AST + f) * 2)));
                    float r0 = sig_t(gir.x + acc[mt][fg][2 * hf]     + bs1[f]);
                    float r1 = sig_t(gir.y + acc[mt][fg][2 * hf + 1] + bs1[f + 1]);
                    float z0 = sig_t(giz.x + acc[mt][3 + fg][2 * hf]     + bs1[96 + f]);
                    float z1 = sig_t(giz.y + acc[mt][3 + fg][2 * hf + 1] + bs1[97 + f]);
                    float n0 = tanhap(gin.x + r0 * (acc[mt][6 + fg][2 * hf]     + bs1[192 + f]));
                    float n1 = tanhap(gin.y + r1 * (acc[mt][6 + fg][2 * hf + 1] + bs1[193 + f]));
                    float2 v;
                    v.x = (1.f - z0) * n0 + z0 * pv.x;
                    v.y = (1.f - z1) * n1 + z1 * pv.y;
                    u32 pk = toh2(v);
                    v1p[mt][hf][fg] = pk;
                    *(u32*)(smem + SM_E + (u32)((r * AST + f) * 2)) = pk;
                }
            }
        }
        CP_WAIT0();
        barg(bid);   // group: A reads done, e1 visible, STG data visible

        // ---- convert STG -> A (group rows) for tile tn ----
        if (tn < ntiles32) {
            #pragma unroll
            for (int q = 0; q < 12; ++q) {
                int i = gt + 128 * q;
                int rl = i / 48, j = i - rl * 48, k = 2 * j;
                *(u32*)(smem + SM_A + (u32)(((32 * wM + rl) * AST + k) * 2))
                    = toh2(*(const float2*)(stg + rl * 96 + k));
            }
        }

        // ============ layer 2 (E rows) ============
        #pragma unroll
        for (int mt = 0; mt < 2; ++mt)
            #pragma unroll
            for (int j = 0; j < 9; ++j)
                #pragma unroll
                for (int c = 0; c < 4; ++c) acc[mt][j][c] = 0.f;

        #pragma unroll
        for (int ks = 0; ks < 6; ++ks) {
            u32 ah[2][4];
            #pragma unroll
            for (int mt = 0; mt < 2; ++mt) {
                u32 ro = (u32)((32 * wM + mt * 16 + a_row) * AST + ks * 16 + a_kof) * 2;
                ldm4(ah[mt], sb + SM_E + ro);
            }
            #pragma unroll
            for (int jp = 0; jp < 4; ++jp) {
                u32 ro = (u32)((wN * 72 + jp * 16 + b4r) * AST + ks * 16 + b_kof) * 2;
                u32 bh[4];
                ldm4(bh, sb + SM_B2 + ro);
                #pragma unroll
                for (int mt = 0; mt < 2; ++mt) {
                    mma_f16(acc[mt][2 * jp],     ah[mt], bh);
                    mma_f16(acc[mt][2 * jp + 1], ah[mt], bh + 2);
                }
            }
            {
                u32 ro = (u32)((wN * 72 + 64 + b_row) * AST + ks * 16 + b_kof) * 2;
                u32 bh[2];
                ldm2(bh, sb + SM_B2 + ro);
                #pragma unroll
                for (int mt = 0; mt < 2; ++mt)
                    mma_f16(acc[mt][8], ah[mt], bh);
            }
        }

        // GRU2 epilogue: gi2 from smem; prev2 = packed e1 regs
        #pragma unroll
        for (int mt = 0; mt < 2; ++mt) {
            #pragma unroll
            for (int hf = 0; hf < 2; ++hf) {
                int rl = mt * 16 + hf * 8 + (lane >> 2);
                size_t ge = e0 + rl;
                int nl = rl >> 4;    // which of the 2 dst nodes
                #pragma unroll
                for (int fg = 0; fg < 3; ++fg) {
                    int f = wN * 24 + fg * 8 + 2 * (lane & 3);
                    uint4 gv = *(const uint4*)(gi2s
                        + (size_t)(nl * 48 + wN * 12 + fg * 4 + (lane & 3)) * 16);
                    float2 gir = __half22float2(*(__half2*)&gv.x);
                    float2 giz = __half22float2(*(__half2*)&gv.y);
                    float2 gin = __half22float2(*(__half2*)&gv.z);
                    float2 pv  = __half22float2(*(__half2*)&v1p[mt][hf][fg]);
                    float r0 = sig_t(gir.x + acc[mt][fg][2 * hf]     + bs2[f]);
                    float r1 = sig_t(gir.y + acc[mt][fg][2 * hf + 1] + bs2[f + 1]);
                    float z0 = sig_t(giz.x + acc[mt][3 + fg][2 * hf]     + bs2[96 + f]);
                    float z1 = sig_t(giz.y + acc[mt][3 + fg][2 * hf + 1] + bs2[97 + f]);
                    float n0 = tanhap(gin.x + r0 * (acc[mt][6 + fg][2 * hf]     + bs2[192 + f]));
                    float n1 = tanhap(gin.y + r1 * (acc[mt][6 + fg][2 * hf + 1] + bs2[193 + f]));
                    float2 v;
                    v.x = (1.f - z0) * n0 + z0 * pv.x;
                    v.y = (1.f - z1) * n1 + z1 * pv.y;
                    oute[ge * 48 + wN * 12 + fg * 4 + (lane & 3)] = toh2(v);
                    s1[fg].x += v.x; s1[fg].y += v.y;
                    s2[fg].x += v.x * v.x; s2[fg].y += v.y * v.y;
                }
            }
        }
        barg(bid);   // conv(A) + E reads done for group before next tile
    }

    __syncthreads();
    #pragma unroll
    for (int fg = 0; fg < 3; ++fg) {
        int f = wN * 24 + fg * 8 + 2 * (lane & 3);
        atomicAdd(&st[f],          s1[fg].x);
        atomicAdd(&st[f + 1],      s1[fg].y);
        atomicAdd(&st[96 + f],     s2[fg].x);
        atomicAdd(&st[96 + f + 1], s2[fg].y);
    }
    __syncthreads();
    if (tid < 192) atomicAdd(&g_stats[192 + tid], st[tid]);
}

// =================== edge-gated aggregation + fused h-BN stats ===================
__global__ void agg_kernel(const float* __restrict__ ef, const int* __restrict__ src,
                           float* __restrict__ hbuf, int Nn, int deg)
{
    __shared__ float s_sum[F], s_sq[F];
    int tid = threadIdx.x;
    if (tid < F) { s_sum[tid] = 0.f; s_sq[tid] = 0.f; }
    __syncthreads();

    int warp = tid >> 5, lane = tid & 31;
    int node = blockIdx.x * 8 + warp;
    if (node < Nn) {
        size_t ebase = (size_t)node * deg;
        int sv = (lane < deg) ? __ldg(&src[ebase + lane]) : 0;
        float num[3] = {0.f, 0.f, 0.f}, den[3] = {0.f, 0.f, 0.f};
        #pragma unroll 8
        for (int e = 0; e < deg; ++e) {
            int s = __shfl_sync(0xFFFFFFFFu, sv, e);
            size_t ge = ebase + e;
            const float* efr = ef + ge * F;
            const float* bh  = g_ab + (size_t)s * 2 * F + F;
            #pragma unroll
            for (int sub = 0; sub < 3; ++sub) {
                int f = lane + sub * 32;
                float sg = sig_t(efr[f]);
                num[sub] += sg * __ldg(&bh[f]);
                den[sub] += sg;
            }
        }
        #pragma unroll
        for (int sub = 0; sub < 3; ++sub) {
            int f = lane + sub * 32;
            float hv = g_ab[(size_t)node * 2 * F + f] + num[sub] / (den[sub] + 1e-6f);
            hbuf[(size_t)node * F + f] = hv;
            atomicAdd(&s_sum[f], hv);
            atomicAdd(&s_sq[f], hv * hv);
        }
    }
    __syncthreads();
    if (tid < F) {
        atomicAdd(&g_stats[tid],     s_sum[tid]);
        atomicAdd(&g_stats[F + tid], s_sq[tid]);
    }
}

// =================== epilogues: residual + ReLU(BatchNorm(.)) ===================
__global__ void h_epi_kernel(const float* __restrict__ x0, const float* __restrict__ hbuf,
                             const float* __restrict__ gamma, const float* __restrict__ beta,
                             float* __restrict__ out, int Nn)
{
    int i = blockIdx.x * blockDim.x + threadIdx.x;
    if (i >= Nn * F) return;
    int f = i % F;
    float invn = 1.f / (float)Nn;
    float m  = g_stats[f] * invn;
    float vv = g_stats[F + f] * invn - m * m;
    float sc = rsqrtf(vv + 1e-5f);
    float v = (hbuf[i] - m) * sc * gamma[f] + beta[f];
    out[i] = x0[i] + fmaxf(v, 0.f);
}

__global__ void e_epi_kernel(const float* __restrict__ ef, const u32* __restrict__ e2h,
                             const float* __restrict__ gamma, const float* __restrict__ beta,
                             float* __restrict__ out, long Ecnt)
{
    long i = (long)blockIdx.x * blockDim.x + threadIdx.x;
    if (i >= Ecnt * 48) return;
    int f = 2 * (int)(i % 48);
    float invn = 1.f / (float)Ecnt;
    float m0 = g_stats[2 * F + f]     * invn;
    float m1 = g_stats[2 * F + f + 1] * invn;
    float v0 = g_stats[3 * F + f]     * invn - m0 * m0;
    float v1 = g_stats[3 * F + f + 1] * invn - m1 * m1;
    float sc0 = rsqrtf(v0 + 1e-5f) * gamma[f];
    float sc1 = rsqrtf(v1 + 1e-5f) * gamma[f + 1];
    u32 pk = e2h[i];
    float2 e2 = __half22float2(*(__half2*)&pk);
    float2 efv = *(const float2*)(ef + 2 * i);
    float2 o;
    o.x = efv.x + fmaxf((e2.x - m0) * sc0 + beta[f],     0.f);
    o.y = efv.y + fmaxf((e2.y - m1) * sc1 + beta[f + 1], 0.f);
    *(float2*)(out + 2 * i) = o;
}

// =================== launch ===================
extern "C" void kernel_launch(void* const* d_in, const int* in_sizes, int n_in,
                              void* d_out, int out_size)
{
    const float* node_feat = (const float*)d_in[0];
    const float* edge_feat = (const float*)d_in[1];
    const int*   src       = (const int*)d_in[2];
    const float* A_w = (const float*)d_in[4];  const float* A_b = (const float*)d_in[5];
    const float* B_w = (const float*)d_in[6];  const float* B_b = (const float*)d_in[7];
    const float* g1_wih = (const float*)d_in[8];  const float* g1_whh = (const float*)d_in[9];
    const float* g1_bih = (const float*)d_in[10]; const float* g1_bhh = (const float*)d_in[11];
    const float* g2_wih = (const float*)d_in[12]; const float* g2_whh = (const float*)d_in[13];
    const float* g2_bih = (const float*)d_in[14]; const float* g2_bhh = (const float*)d_in[15];
    const float* bnhg = (const float*)d_in[16]; const float* bnhb = (const float*)d_in[17];
    const float* bneg = (const float*)d_in[18]; const float* bneb = (const float*)d_in[19];

    int Nn   = in_sizes[0] / F;
    int Ecnt = in_sizes[2];
    int deg  = Ecnt / Nn;
    float* out = (float*)d_out;

    float *ab, *hbuf, *gi1, *gi2;
    u32* e2h;
    cudaGetSymbolAddress((void**)&ab,   g_ab);
    cudaGetSymbolAddress((void**)&hbuf, g_h);
    cudaGetSymbolAddress((void**)&gi1,  g_gi1);
    cudaGetSymbolAddress((void**)&gi2,  g_gi2);
    cudaGetSymbolAddress((void**)&e2h,  g_e2h);

    int smAB = 192 * AST * 2 + 26624 + 192 * 4;             // 67328
    cudaFuncSetAttribute(gemm_ab_f16,   cudaFuncAttributeMaxDynamicSharedMemorySize, smAB);
    cudaFuncSetAttribute(gemm_gi_f16g,  cudaFuncAttributeMaxDynamicSharedMemorySize, GIK_TOT);
    cudaFuncSetAttribute(edge_gru2_mma, cudaFuncAttributeMaxDynamicSharedMemorySize, SM_TOT);

    zero_stats_kernel<<<1, 4 * F>>>();

    int ntN = (Nn + 127) / 128;
    int gN  = ntN < 148 ? ntN : 148;
    gemm_ab_f16<<<gN, 512, smAB>>>(node_feat, A_w, B_w, A_b, B_b, ab, Nn, ntN);
    agg_kernel<<<(Nn + 7) / 8, 256>>>(edge_feat, src, hbuf, Nn, deg);
    gemm_gi_f16g<<<gN, 512, GIK_TOT>>>(hbuf, g1_wih, g1_bih, g2_wih, g2_bih,
                                       (uint4*)gi1, (uint4*)gi2, Nn, ntN);

    int ntE32 = Ecnt / 32;   // 25000 independent 32-edge tiles
    edge_gru2_mma<<<148, 512, SM_TOT>>>(edge_feat, (const uint4*)gi1, (const uint4*)gi2,
                                        src, g1_whh, g1_bhh, g2_whh, g2_bhh,
                                        e2h, ntE32);

    h_epi_kernel<<<(Nn * F + 255) / 256, 256>>>(node_feat, hbuf, bnhg, bnhb, out, Nn);
    long tot = (long)Ecnt * 48;
    e_epi_kernel<<<(int)((tot + 255) / 256), 256>>>(edge_feat, e2h, bneg, bneb,
                                                    out + (size_t)Nn * F, (long)Ecnt);
}

// round 16
// speedup vs baseline: 1.0268x; 1.0268x over previous
#include <cuda_runtime.h>
#include <cuda_bf16.h>
#include <cuda_fp16.h>
#include <cstdint>

#define F 96
#define G3 288            // 3*F
#define NN 50000
#define EE 800000

typedef unsigned long long u64;
typedef unsigned int u32;

// ---------------- scratch (static __device__ — no allocs allowed) ----------------
__device__ float g_ab [NN * 2 * F];   // [N,192]: cols 0..95 = Ah, 96..191 = Bh
__device__ float g_h  [NN * F];       // aggregated node state
__device__ float g_gi1[NN * G3];      // used as uint4[NN][48]: {r,z,n,pad} half2 per feature pair
__device__ float g_gi2[NN * G3];
__device__ u32   g_e2h[(size_t)EE * 48];   // e2 in half2 pairs
__device__ float g_stats[4 * F];      // [hsum, hsumsq, esum, esumsq]

__device__ __forceinline__ float tanhap(float x) {        // 1 MUFU op
    float y;
    asm("tanh.approx.f32 %0, %1;" : "=f"(y) : "f"(x));
    return y;
}
__device__ __forceinline__ float sig_t(float x) {         // 1 MUFU + 2 FMA
    return fmaf(tanhap(0.5f * x), 0.5f, 0.5f);
}
__device__ __forceinline__ u32 smem_u32(const void* p) {
    u32 a;
    asm("{ .reg .u64 t; cvta.to.shared.u64 t, %1; cvt.u32.u64 %0, t; }" : "=r"(a) : "l"(p));
    return a;
}
__device__ __forceinline__ void barg(int id) {            // 4-warp group barrier
    asm volatile("bar.sync %0, %1;" :: "r"(id), "r"(128) : "memory");
}
__device__ __forceinline__ void cpasync16(u32 s, const void* g) {
    asm volatile("cp.async.cg.shared.global [%0], [%1], 16;" :: "r"(s), "l"(g));
}
#define CP_COMMIT() asm volatile("cp.async.commit_group;" ::: "memory")
#define CP_WAIT0()  asm volatile("cp.async.wait_group 0;" ::: "memory")

// warp-level tensor ops (portable PTX at compute_103 -> HMMA on sm_103a)
__device__ __forceinline__ void ldm4(u32* r, u32 a) {
    asm volatile("ldmatrix.sync.aligned.m8n8.x4.shared.b16 {%0,%1,%2,%3}, [%4];"
        : "=r"(r[0]), "=r"(r[1]), "=r"(r[2]), "=r"(r[3]) : "r"(a));
}
__device__ __forceinline__ void ldm2(u32* r, u32 a) {
    asm volatile("ldmatrix.sync.aligned.m8n8.x2.shared.b16 {%0,%1}, [%2];"
        : "=r"(r[0]), "=r"(r[1]) : "r"(a));
}
__device__ __forceinline__ void mma_f16(float* c, const u32* a, const u32* b) {
    asm volatile("mma.sync.aligned.m16n8k16.row.col.f32.f16.f16.f32 "
        "{%0,%1,%2,%3}, {%4,%5,%6,%7}, {%8,%9}, {%0,%1,%2,%3};"
        : "+f"(c[0]), "+f"(c[1]), "+f"(c[2]), "+f"(c[3])
        : "r"(a[0]), "r"(a[1]), "r"(a[2]), "r"(a[3]), "r"(b[0]), "r"(b[1]));
}

__global__ void zero_stats_kernel() { g_stats[threadIdx.x] = 0.f; }

__device__ __forceinline__ u32 toh2(float2 x) {
    __half2 h = __floats2half2_rn(x.x, x.y);
    return *(u32*)&h;
}
// gate-interleave permutation of a [288] row index
__device__ __forceinline__ int permute_row(int n) {
    int g = n / 96, rem = n - g * 96, w = rem / 24, t = rem - w * 24;
    return w * 72 + ((t >> 3) + 3 * g) * 8 + (t & 7);
}

#define AST 104    // padded smem row stride in 16-bit units (208B, conflict-free ldmatrix)

// =================== fp16 AB GEMM: Y[R,192] = X @ [A_w;B_w].T + [A_b;B_b] ===================
__global__ __launch_bounds__(512)
void gemm_ab_f16(const float* __restrict__ X,
                 const float* __restrict__ W0, const float* __restrict__ W1,
                 const float* __restrict__ b0, const float* __restrict__ b1,
                 float* __restrict__ Y, int R, int ntiles)
{
    constexpr int COUT = 192, NT = 6;
    constexpr int BSZ = COUT * AST * 2;    // 39936
    extern __shared__ char smem[];
    u32 sb = smem_u32(smem);
    const int OF_A = BSZ, OF_BS = BSZ + 26624;
    float* bs = (float*)(smem + OF_BS);
    int tid = threadIdx.x, wid = tid >> 5, lane = tid & 31;

    for (int i = tid; i < COUT * 48; i += 512) {
        int n = i / 48, j = i - n * 48, k = 2 * j;
        float2 w2 = (n < 96) ? *(const float2*)(W0 + n * F + k)
                             : *(const float2*)(W1 + (n - 96) * F + k);
        *(u32*)(smem + (u32)(n * AST + k) * 2) = toh2(w2);
    }
    for (int i = tid; i < COUT; i += 512)
        bs[i] = (i < 96) ? b0[i] : b1[i - 96];
    __syncthreads();

    int wM = wid & 3, wN = wid >> 2;
    int a_row = ((lane >> 3) & 1) * 8 + (lane & 7);
    int a_kof = (lane >> 4) * 8;
    int b4r   = (lane & 7) + ((lane >> 4) << 3);

    for (int t = blockIdx.x; t < ntiles; t += gridDim.x) {
        int base = t * 128;
        #pragma unroll
        for (int q = 0; q < 12; ++q) {
            int i = tid + 512 * q;
            int r = i / 48, j = i - r * 48, k = 2 * j;
            float2 x2 = (base + r < R) ? *(const float2*)(X + (size_t)(base + r) * F + k)
                                       : make_float2(0.f, 0.f);
            *(u32*)(smem + OF_A + (u32)(r * AST + k) * 2) = toh2(x2);
        }
        __syncthreads();

        float acc[2][NT][4];
        #pragma unroll
        for (int mt = 0; mt < 2; ++mt)
            #pragma unroll
            for (int j = 0; j < NT; ++j)
                #pragma unroll
                for (int c = 0; c < 4; ++c) acc[mt][j][c] = 0.f;

        #pragma unroll
        for (int ks = 0; ks < 6; ++ks) {
            u32 ah[2][4];
            #pragma unroll
            for (int mt = 0; mt < 2; ++mt) {
                u32 ro = (u32)((32 * wM + mt * 16 + a_row) * AST + ks * 16 + a_kof) * 2;
                ldm4(ah[mt], sb + OF_A + ro);
            }
            #pragma unroll
            for (int jp = 0; jp < 3; ++jp) {
                u32 ro = (u32)((wN * 48 + jp * 16 + b4r) * AST + ks * 16
                               + ((lane >> 3) & 1) * 8) * 2;
                u32 bh[4];
                ldm4(bh, sb + ro);
                #pragma unroll
                for (int mt = 0; mt < 2; ++mt) {
                    mma_f16(acc[mt][2 * jp],     ah[mt], bh);
                    mma_f16(acc[mt][2 * jp + 1], ah[mt], bh + 2);
                }
            }
        }

        #pragma unroll
        for (int mt = 0; mt < 2; ++mt)
            #pragma unroll
            for (int hf = 0; hf < 2; ++hf) {
                int r = base + 32 * wM + mt * 16 + hf * 8 + (lane >> 2);
                if (r < R) {
                    #pragma unroll
                    for (int j = 0; j < NT; ++j) {
                        int f = wN * 48 + j * 8 + 2 * (lane & 3);
                        float2 v;
                        v.x = acc[mt][j][2 * hf]     + bs[f];
                        v.y = acc[mt][j][2 * hf + 1] + bs[f + 1];
                        *(float2*)(Y + (size_t)r * COUT + f) = v;
                    }
                }
            }
        __syncthreads();
    }
}

// =================== merged fp16 gi GEMM: both W1/W2, shared A conversion ===================
#define GIK_B1 0            // 59904
#define GIK_B2 59904        // -> 119808
#define GIK_A  119808       // 26624 -> 146432
#define GIK_BS 146432       // 2*288 floats -> +2304 = 148736
#define GIK_TOT 148736

__global__ __launch_bounds__(512)
void gemm_gi_f16g(const float* __restrict__ X,
                  const float* __restrict__ W1, const float* __restrict__ b1,
                  const float* __restrict__ W2, const float* __restrict__ b2,
                  uint4* __restrict__ Y1, uint4* __restrict__ Y2, int R, int ntiles)
{
    extern __shared__ char smem[];
    u32 sb = smem_u32(smem);
    float* bsP = (float*)(smem + GIK_BS);
    int tid = threadIdx.x, wid = tid >> 5, lane = tid & 31;

    for (int i = tid; i < G3 * 48; i += 512) {
        int n = i / 48, j = i - n * 48, k = 2 * j;
        int p = permute_row(n);
        u32 off = (u32)(p * AST + k) * 2;
        *(u32*)(smem + GIK_B1 + off) = toh2(*(const float2*)(W1 + n * F + k));
        *(u32*)(smem + GIK_B2 + off) = toh2(*(const float2*)(W2 + n * F + k));
    }
    for (int i = tid; i < G3; i += 512) {
        bsP[permute_row(i)]       = b1[i];
        bsP[288 + permute_row(i)] = b2[i];
    }
    __syncthreads();

    int wM = wid & 3, wN = wid >> 2;
    int a_row = ((lane >> 3) & 1) * 8 + (lane & 7);
    int a_kof = (lane >> 4) * 8;
    int b4r   = (lane & 7) + ((lane >> 4) << 3);
    int b_row = lane & 7;
    int b_kof = ((lane >> 3) & 1) * 8;

    for (int t = blockIdx.x; t < ntiles; t += gridDim.x) {
        int base = t * 128;
        #pragma unroll
        for (int q = 0; q < 12; ++q) {
            int i = tid + 512 * q;
            int r = i / 48, j = i - r * 48, k = 2 * j;
            float2 x2 = (base + r < R) ? *(const float2*)(X + (size_t)(base + r) * F + k)
                                       : make_float2(0.f, 0.f);
            *(u32*)(smem + GIK_A + (u32)(r * AST + k) * 2) = toh2(x2);
        }
        __syncthreads();

        #pragma unroll
        for (int gg = 0; gg < 2; ++gg) {
            u32 bb = sb + (gg ? GIK_B2 : GIK_B1);
            const float* bsc = bsP + gg * 288;
            uint4* Yo = gg ? Y2 : Y1;

            float acc[2][9][4];
            #pragma unroll
            for (int mt = 0; mt < 2; ++mt)
                #pragma unroll
                for (int j = 0; j < 9; ++j)
                    #pragma unroll
                    for (int c = 0; c < 4; ++c) acc[mt][j][c] = 0.f;

            #pragma unroll
            for (int ks = 0; ks < 6; ++ks) {
                u32 ah[2][4];
                #pragma unroll
                for (int mt = 0; mt < 2; ++mt) {
                    u32 ro = (u32)((32 * wM + mt * 16 + a_row) * AST + ks * 16 + a_kof) * 2;
                    ldm4(ah[mt], sb + GIK_A + ro);
                }
                #pragma unroll
                for (int jp = 0; jp < 4; ++jp) {
                    u32 ro = (u32)((wN * 72 + jp * 16 + b4r) * AST + ks * 16 + b_kof) * 2;
                    u32 bh[4];
                    ldm4(bh, bb + ro);
                    #pragma unroll
                    for (int mt = 0; mt < 2; ++mt) {
                        mma_f16(acc[mt][2 * jp],     ah[mt], bh);
                        mma_f16(acc[mt][2 * jp + 1], ah[mt], bh + 2);
                    }
                }
                {
                    u32 ro = (u32)((wN * 72 + 64 + b_row) * AST + ks * 16 + b_kof) * 2;
                    u32 bh[2];
                    ldm2(bh, bb + ro);
                    #pragma unroll
                    for (int mt = 0; mt < 2; ++mt)
                        mma_f16(acc[mt][8], ah[mt], bh);
                }
            }

            #pragma unroll
            for (int mt = 0; mt < 2; ++mt)
                #pragma unroll
                for (int hf = 0; hf < 2; ++hf) {
                    int r = base + 32 * wM + mt * 16 + hf * 8 + (lane >> 2);
                    if (r < R) {
                        #pragma unroll
                        for (int fg = 0; fg < 3; ++fg) {
                            int c = wN * 72 + fg * 8 + 2 * (lane & 3);
                            float2 vr, vz, vn;
                            vr.x = acc[mt][fg][2 * hf]         + bsc[c];
                            vr.y = acc[mt][fg][2 * hf + 1]     + bsc[c + 1];
                            vz.x = acc[mt][3 + fg][2 * hf]     + bsc[c + 24];
                            vz.y = acc[mt][3 + fg][2 * hf + 1] + bsc[c + 25];
                            vn.x = acc[mt][6 + fg][2 * hf]     + bsc[c + 48];
                            vn.y = acc[mt][6 + fg][2 * hf + 1] + bsc[c + 49];
                            uint4 o;
                            o.x = toh2(vr); o.y = toh2(vz); o.z = toh2(vn); o.w = 0;
                            Yo[(size_t)r * 48 + wN * 12 + fg * 4 + (lane & 3)] = o;
                        }
                    }
                }
        }
        __syncthreads();
    }
}

// =================== FUSED fp16 edge kernel: 2 barriers/tile, cp.async staging (R14) =========
#define SM_B1  0            // 59904
#define SM_B2  59904        // -> 119808
#define SM_A   119808       // 26624 -> 146432
#define SM_E   146432       // 26624 -> 173056
#define SM_STG 173056       // 49152 -> 222208
#define SM_BS  222208       // 2304 -> 224512
#define SM_ST  224512       // 768 -> 225280
#define SM_GI2 225280       // 6144 -> 231424
#define SM_TOT 231424

__global__ __launch_bounds__(512)
void edge_gru2_mma(const float* __restrict__ ef,
                   const uint4* __restrict__ gi1_all, const uint4* __restrict__ gi2_all,
                   const int* __restrict__ src,
                   const float* __restrict__ W1, const float* __restrict__ b1,
                   const float* __restrict__ W2, const float* __restrict__ b2,
                   u32* __restrict__ oute, int ntiles)
{
    extern __shared__ char smem[];
    u32 sb = smem_u32(smem);
    int tid = threadIdx.x, wid = tid >> 5, lane = tid & 31;
    float* bs1 = (float*)(smem + SM_BS);
    float* bs2 = bs1 + G3;
    float* st  = (float*)(smem + SM_ST);
    float* stg = (float*)(smem + SM_STG);

    int wM = wid & 3, wN = wid >> 2;
    int gt = wN * 32 + lane;
    int bid = 1 + wM;

    // ---- W1, W2 -> permuted fp16 (once per block) ----
    for (int i = tid; i < G3 * 48; i += 512) {
        int n = i / 48, j = i - n * 48, k = 2 * j;
        int p = permute_row(n);
        u32 off = (u32)(p * AST + k) * 2;
        *(u32*)(smem + SM_B1 + off) = toh2(*(const float2*)(W1 + n * F + k));
        *(u32*)(smem + SM_B2 + off) = toh2(*(const float2*)(W2 + n * F + k));
    }
    for (int i = tid; i < G3; i += 512) { bs1[i] = b1[i]; bs2[i] = b2[i]; }
    if (tid < 192) st[tid] = 0.f;

    // prologue: group converts its rows of the first tile into A
    if (blockIdx.x < ntiles) {
        size_t e0 = (size_t)blockIdx.x * 128;
        #pragma unroll
        for (int q = 0; q < 12; ++q) {
            int i = gt + 128 * q;
            int rl = i / 48, j = i - rl * 48, k = 2 * j;
            int r = 32 * wM + rl;
            *(u32*)(smem + SM_A + (u32)(r * AST + k) * 2)
                = toh2(*(const float2*)(ef + (e0 + r) * F + k));
        }
    }
    __syncthreads();

    int a_row = ((lane >> 3) & 1) * 8 + (lane & 7);
    int a_kof = (lane >> 4) * 8;
    int b4r   = (lane & 7) + ((lane >> 4) << 3);
    int b_row = lane & 7;
    int b_kof = ((lane >> 3) & 1) * 8;
    float2 s1[3], s2[3];
    #pragma unroll
    for (int i = 0; i < 3; ++i) { s1[i] = make_float2(0.f, 0.f); s2[i] = make_float2(0.f, 0.f); }

    char* gi2s = smem + SM_GI2 + wM * 2 * 48 * 16;

    for (int t = blockIdx.x; t < ntiles; t += gridDim.x) {
        size_t e0 = (size_t)t * 128;
        int tn = t + gridDim.x;

        // ---- cp.async next raw tile (group rows) into STG ----
        if (tn < ntiles) {
            const char* gsrc = (const char*)(ef + (size_t)tn * 128 * F) + wM * 12288;
            u32 sdst = sb + SM_STG + (u32)wM * 12288;
            #pragma unroll
            for (int q = 0; q < 6; ++q) {
                int i = gt + 128 * q;
                cpasync16(sdst + i * 16, gsrc + i * 16);
            }
        }
        CP_COMMIT();

        // ---- stage gi2 for the group's 2 dst nodes (dst = edge/16) ----
        if (gt < 96) {
            int nl = gt / 48, pr = gt - nl * 48;
            int node = (int)(e0 >> 4) + 2 * wM + nl;
            *(uint4*)(gi2s + (size_t)(nl * 48 + pr) * 16)
                = __ldg(gi2_all + (size_t)node * 48 + pr);
        }
        // ---- prefetch src indices / gi1 row pointers ----
        const uint4* gi1p[4];
        #pragma unroll
        for (int mh = 0; mh < 4; ++mh) {
            int r = 32 * wM + (mh >> 1) * 16 + (mh & 1) * 8 + (lane >> 2);
            gi1p[mh] = gi1_all + (size_t)__ldg(&src[e0 + r]) * 48;
        }

        float acc[2][9][4];
        u32 v1p[2][2][3];

        // ============ layer 1 (A) ============
        #pragma unroll
        for (int mt = 0; mt < 2; ++mt)
            #pragma unroll
            for (int j = 0; j < 9; ++j)
                #pragma unroll
                for (int c = 0; c < 4; ++c) acc[mt][j][c] = 0.f;

        #pragma unroll
        for (int ks = 0; ks < 6; ++ks) {
            u32 ah[2][4];
            #pragma unroll
            for (int mt = 0; mt < 2; ++mt) {
                u32 ro = (u32)((32 * wM + mt * 16 + a_row) * AST + ks * 16 + a_kof) * 2;
                ldm4(ah[mt], sb + SM_A + ro);
            }
            #pragma unroll
            for (int jp = 0; jp < 4; ++jp) {
                u32 ro = (u32)((wN * 72 + jp * 16 + b4r) * AST + ks * 16 + b_kof) * 2;
                u32 bh[4];
                ldm4(bh, sb + SM_B1 + ro);
                #pragma unroll
                for (int mt = 0; mt < 2; ++mt) {
                    mma_f16(acc[mt][2 * jp],     ah[mt], bh);
                    mma_f16(acc[mt][2 * jp + 1], ah[mt], bh + 2);
                }
            }
            {
                u32 ro = (u32)((wN * 72 + 64 + b_row) * AST + ks * 16 + b_kof) * 2;
                u32 bh[2];
                ldm2(bh, sb + SM_B1 + ro);
                #pragma unroll
                for (int mt = 0; mt < 2; ++mt)
                    mma_f16(acc[mt][8], ah[mt], bh);
            }
        }

        // GRU1 epilogue -> v1p; store e1 into E (separate buffer, no hazard with A)
        #pragma unroll
        for (int mt = 0; mt < 2; ++mt) {
            #pragma unroll
            for (int hf = 0; hf < 2; ++hf) {
                int r = 32 * wM + mt * 16 + hf * 8 + (lane >> 2);
                const uint4* gi = gi1p[mt * 2 + hf];
                #pragma unroll
                for (int fg = 0; fg < 3; ++fg) {
                    int f = wN * 24 + fg * 8 + 2 * (lane & 3);
                    uint4 gv = __ldg(gi + wN * 12 + fg * 4 + (lane & 3));
                    float2 gir = __half22float2(*(__half2*)&gv.x);
                    float2 giz = __half22float2(*(__half2*)&gv.y);
                    float2 gin = __half22float2(*(__half2*)&gv.z);
                    float2 pv  = __half22float2(*(__half2*)(smem + SM_A + (u32)((r * AST + f) * 2)));
                    float r0 = sig_t(gir.x + acc[mt][fg][2 * hf]     + bs1[f]);
                    float r1 = sig_t(gir.y + acc[mt][fg][2 * hf + 1] + bs1[f + 1]);
                    float z0 = sig_t(giz.x + acc[mt][3 + fg][2 * hf]     + bs1[96 + f]);
                    float z1 = sig_t(giz.y + acc[mt][3 + fg][2 * hf + 1] + bs1[97 + f]);
                    float n0 = tanhap(gin.x + r0 * (acc[mt][6 + fg][2 * hf]     + bs1[192 + f]));
                    float n1 = tanhap(gin.y + r1 * (acc[mt][6 + fg][2 * hf + 1] + bs1[193 + f]));
                    float2 v;
                    v.x = (1.f - z0) * n0 + z0 * pv.x;
                    v.y = (1.f - z1) * n1 + z1 * pv.y;
                    u32 pk = toh2(v);
                    v1p[mt][hf][fg] = pk;
                    *(u32*)(smem + SM_E + (u32)((r * AST + f) * 2)) = pk;
                }
            }
        }
        CP_WAIT0();
        barg(bid);   // group: A reads done, e1 visible, STG data visible

        // ---- convert STG -> A for tile tn (A is dead for this tile now) ----
        if (tn < ntiles) {
            #pragma unroll
            for (int q = 0; q < 12; ++q) {
                int i = gt + 128 * q;
                int rl = i / 48, j = i - rl * 48, k = 2 * j;
                int r = 32 * wM + rl;
                *(u32*)(smem + SM_A + (u32)(r * AST + k) * 2)
                    = toh2(*(const float2*)(stg + r * 96 + k));
            }
        }

        // ============ layer 2 (E) ============
        #pragma unroll
        for (int mt = 0; mt < 2; ++mt)
            #pragma unroll
            for (int j = 0; j < 9; ++j)
                #pragma unroll
                for (int c = 0; c < 4; ++c) acc[mt][j][c] = 0.f;

        #pragma unroll
        for (int ks = 0; ks < 6; ++ks) {
            u32 ah[2][4];
            #pragma unroll
            for (int mt = 0; mt < 2; ++mt) {
                u32 ro = (u32)((32 * wM + mt * 16 + a_row) * AST + ks * 16 + a_kof) * 2;
                ldm4(ah[mt], sb + SM_E + ro);
            }
            #pragma unroll
            for (int jp = 0; jp < 4; ++jp) {
                u32 ro = (u32)((wN * 72 + jp * 16 + b4r) * AST + ks * 16 + b_kof) * 2;
                u32 bh[4];
                ldm4(bh, sb + SM_B2 + ro);
                #pragma unroll
                for (int mt = 0; mt < 2; ++mt) {
                    mma_f16(acc[mt][2 * jp],     ah[mt], bh);
                    mma_f16(acc[mt][2 * jp + 1], ah[mt], bh + 2);
                }
            }
            {
                u32 ro = (u32)((wN * 72 + 64 + b_row) * AST + ks * 16 + b_kof) * 2;
                u32 bh[2];
                ldm2(bh, sb + SM_B2 + ro);
                #pragma unroll
                for (int mt = 0; mt < 2; ++mt)
                    mma_f16(acc[mt][8], ah[mt], bh);
            }
        }

        // GRU2 epilogue: gi2 from smem; prev2 = packed e1 regs
        #pragma unroll
        for (int mt = 0; mt < 2; ++mt) {
            #pragma unroll
            for (int hf = 0; hf < 2; ++hf) {
                int r = 32 * wM + mt * 16 + hf * 8 + (lane >> 2);
                size_t ge = e0 + r;
                #pragma unroll
                for (int fg = 0; fg < 3; ++fg) {
                    int f = wN * 24 + fg * 8 + 2 * (lane & 3);
                    uint4 gv = *(const uint4*)(gi2s
                        + (size_t)(mt * 48 + wN * 12 + fg * 4 + (lane & 3)) * 16);
                    float2 gir = __half22float2(*(__half2*)&gv.x);
                    float2 giz = __half22float2(*(__half2*)&gv.y);
                    float2 gin = __half22float2(*(__half2*)&gv.z);
                    float2 pv  = __half22float2(*(__half2*)&v1p[mt][hf][fg]);
                    float r0 = sig_t(gir.x + acc[mt][fg][2 * hf]     + bs2[f]);
                    float r1 = sig_t(gir.y + acc[mt][fg][2 * hf + 1] + bs2[f + 1]);
                    float z0 = sig_t(giz.x + acc[mt][3 + fg][2 * hf]     + bs2[96 + f]);
                    float z1 = sig_t(giz.y + acc[mt][3 + fg][2 * hf + 1] + bs2[97 + f]);
                    float n0 = tanhap(gin.x + r0 * (acc[mt][6 + fg][2 * hf]     + bs2[192 + f]));
                    float n1 = tanhap(gin.y + r1 * (acc[mt][6 + fg][2 * hf + 1] + bs2[193 + f]));
                    float2 v;
                    v.x = (1.f - z0) * n0 + z0 * pv.x;
                    v.y = (1.f - z1) * n1 + z1 * pv.y;
                    oute[ge * 48 + wN * 12 + fg * 4 + (lane & 3)] = toh2(v);
                    s1[fg].x += v.x; s1[fg].y += v.y;
                    s2[fg].x += v.x * v.x; s2[fg].y += v.y * v.y;
                }
            }
        }
        barg(bid);   // conv(A) complete + E reads done for group before next tile
    }

    __syncthreads();
    #pragma unroll
    for (int fg = 0; fg < 3; ++fg) {
        int f = wN * 24 + fg * 8 + 2 * (lane & 3);
        atomicAdd(&st[f],          s1[fg].x);
        atomicAdd(&st[f + 1],      s1[fg].y);
        atomicAdd(&st[96 + f],     s2[fg].x);
        atomicAdd(&st[96 + f + 1], s2[fg].y);
    }
    __syncthreads();
    if (tid < 192) atomicAdd(&g_stats[192 + tid], st[tid]);
}

// =================== edge-gated aggregation + fused h-BN stats ===================
__global__ void agg_kernel(const float* __restrict__ ef, const int* __restrict__ src,
                           float* __restrict__ hbuf, int Nn, int deg)
{
    __shared__ float s_sum[F], s_sq[F];
    int tid = threadIdx.x;
    if (tid < F) { s_sum[tid] = 0.f; s_sq[tid] = 0.f; }
    __syncthreads();

    int warp = tid >> 5, lane = tid & 31;
    int node = blockIdx.x * 8 + warp;
    if (node < Nn) {
        size_t ebase = (size_t)node * deg;
        int sv = (lane < deg) ? __ldg(&src[ebase + lane]) : 0;
        float num[3] = {0.f, 0.f, 0.f}, den[3] = {0.f, 0.f, 0.f};
        #pragma unroll 8
        for (int e = 0; e < deg; ++e) {
            int s = __shfl_sync(0xFFFFFFFFu, sv, e);
            size_t ge = ebase + e;
            const float* efr = ef + ge * F;
            const float* bh  = g_ab + (size_t)s * 2 * F + F;
            #pragma unroll
            for (int sub = 0; sub < 3; ++sub) {
                int f = lane + sub * 32;
                float sg = sig_t(efr[f]);
                num[sub] += sg * __ldg(&bh[f]);
                den[sub] += sg;
            }
        }
        #pragma unroll
        for (int sub = 0; sub < 3; ++sub) {
            int f = lane + sub * 32;
            float hv = g_ab[(size_t)node * 2 * F + f] + num[sub] / (den[sub] + 1e-6f);
            hbuf[(size_t)node * F + f] = hv;
            atomicAdd(&s_sum[f], hv);
            atomicAdd(&s_sq[f], hv * hv);
        }
    }
    __syncthreads();
    if (tid < F) {
        atomicAdd(&g_stats[tid],     s_sum[tid]);
        atomicAdd(&g_stats[F + tid], s_sq[tid]);
    }
}

// =================== epilogues: residual + ReLU(BatchNorm(.)) ===================
__global__ void h_epi_kernel(const float* __restrict__ x0, const float* __restrict__ hbuf,
                             const float* __restrict__ gamma, const float* __restrict__ beta,
                             float* __restrict__ out, int Nn)
{
    int i = blockIdx.x * blockDim.x + threadIdx.x;
    if (i >= Nn * F) return;
    int f = i % F;
    float invn = 1.f / (float)Nn;
    float m  = g_stats[f] * invn;
    float vv = g_stats[F + f] * invn - m * m;
    float sc = rsqrtf(vv + 1e-5f);
    float v = (hbuf[i] - m) * sc * gamma[f] + beta[f];
    out[i] = x0[i] + fmaxf(v, 0.f);
}

__global__ void e_epi_kernel(const float* __restrict__ ef, const u32* __restrict__ e2h,
                             const float* __restrict__ gamma, const float* __restrict__ beta,
                             float* __restrict__ out, long Ecnt)
{
    long i = (long)blockIdx.x * blockDim.x + threadIdx.x;
    if (i >= Ecnt * 48) return;
    int f = 2 * (int)(i % 48);
    float invn = 1.f / (float)Ecnt;
    float m0 = g_stats[2 * F + f]     * invn;
    float m1 = g_stats[2 * F + f + 1] * invn;
    float v0 = g_stats[3 * F + f]     * invn - m0 * m0;
    float v1 = g_stats[3 * F + f + 1] * invn - m1 * m1;
    float sc0 = rsqrtf(v0 + 1e-5f) * gamma[f];
    float sc1 = rsqrtf(v1 + 1e-5f) * gamma[f + 1];
    u32 pk = e2h[i];
    float2 e2 = __half22float2(*(__half2*)&pk);
    float2 efv = *(const float2*)(ef + 2 * i);
    float2 o;
    o.x = efv.x + fmaxf((e2.x - m0) * sc0 + beta[f],     0.f);
    o.y = efv.y + fmaxf((e2.y - m1) * sc1 + beta[f + 1], 0.f);
    *(float2*)(out + 2 * i) = o;
}

// =================== launch ===================
extern "C" void kernel_launch(void* const* d_in, const int* in_sizes, int n_in,
                              void* d_out, int out_size)
{
    const float* node_feat = (const float*)d_in[0];
    const float* edge_feat = (const float*)d_in[1];
    const int*   src       = (const int*)d_in[2];
    const float* A_w = (const float*)d_in[4];  const float* A_b = (const float*)d_in[5];
    const float* B_w = (const float*)d_in[6];  const float* B_b = (const float*)d_in[7];
    const float* g1_wih = (const float*)d_in[8];  const float* g1_whh = (const float*)d_in[9];
    const float* g1_bih = (const float*)d_in[10]; const float* g1_bhh = (const float*)d_in[11];
    const float* g2_wih = (const float*)d_in[12]; const float* g2_whh = (const float*)d_in[13];
    const float* g2_bih = (const float*)d_in[14]; const float* g2_bhh = (const float*)d_in[15];
    const float* bnhg = (const float*)d_in[16]; const float* bnhb = (const float*)d_in[17];
    const float* bneg = (const float*)d_in[18]; const float* bneb = (const float*)d_in[19];

    int Nn   = in_sizes[0] / F;
    int Ecnt = in_sizes[2];
    int deg  = Ecnt / Nn;
    float* out = (float*)d_out;

    float *ab, *hbuf, *gi1, *gi2;
    u32* e2h;
    cudaGetSymbolAddress((void**)&ab,   g_ab);
    cudaGetSymbolAddress((void**)&hbuf, g_h);
    cudaGetSymbolAddress((void**)&gi1,  g_gi1);
    cudaGetSymbolAddress((void**)&gi2,  g_gi2);
    cudaGetSymbolAddress((void**)&e2h,  g_e2h);

    int smAB = 192 * AST * 2 + 26624 + 192 * 4;             // 67328
    cudaFuncSetAttribute(gemm_ab_f16,   cudaFuncAttributeMaxDynamicSharedMemorySize, smAB);
    cudaFuncSetAttribute(gemm_gi_f16g,  cudaFuncAttributeMaxDynamicSharedMemorySize, GIK_TOT);
    cudaFuncSetAttribute(edge_gru2_mma, cudaFuncAttributeMaxDynamicSharedMemorySize, SM_TOT);

    zero_stats_kernel<<<1, 4 * F>>>();

    int ntN = (Nn + 127) / 128;
    int gN  = ntN < 148 ? ntN : 148;
    gemm_ab_f16<<<gN, 512, smAB>>>(node_feat, A_w, B_w, A_b, B_b, ab, Nn, ntN);
    agg_kernel<<<(Nn + 7) / 8, 256>>>(edge_feat, src, hbuf, Nn, deg);
    gemm_gi_f16g<<<gN, 512, GIK_TOT>>>(hbuf, g1_wih, g1_bih, g2_wih, g2_bih,
                                       (uint4*)gi1, (uint4*)gi2, Nn, ntN);

    int ntE = Ecnt / 128;   // 6250
    edge_gru2_mma<<<148, 512, SM_TOT>>>(edge_feat, (const uint4*)gi1, (const uint4*)gi2,
                                        src, g1_whh, g1_bhh, g2_whh, g2_bhh,
                                        e2h, ntE);

    h_epi_kernel<<<(Nn * F + 255) / 256, 256>>>(node_feat, hbuf, bnhg, bnhb, out, Nn);
    long tot = (long)Ecnt * 48;
    e_epi_kernel<<<(int)((tot + 255) / 256), 256>>>(edge_feat, e2h, bneg, bneb,
                                                    out + (size_t)Nn * F, (long)Ecnt);
}